// round 16
// baseline (speedup 1.0000x reference)
#include <cuda_runtime.h>

// Batched per-object 3-layer MLP — 3 kernels, PDL-chained.
// R16: K1 software-pipelined — each warp covers 16 rows in two 8-row batches,
// issuing batch i+1's loads BEFORE reducing batch i so DRAM queues never
// drain during the SHFL bursts (anti-convoy). K2/K3 identical to R14.
//
//   K1: y1 = W1 @ x + b1                    (256 MB stream)
//   K2: 32 rows of y2 per CTA + W3 partial  (512 MB stream)
//   K3: out[o] = sigmoid(sum partials + b3)

#define N_OBJ_  2048
#define IN_DIM_ 128
#define MID_    256

__device__ float g_y1[N_OBJ_ * MID_];
__device__ float g_part[8 * N_OBJ_];   // [chunk][object]

__device__ __forceinline__ float dot4(float4 a, float4 b) {
    return fmaf(a.x, b.x, fmaf(a.y, b.y, fmaf(a.z, b.z, a.w * b.w)));
}

__device__ __forceinline__ float sigmoidf_(float t) {
    return 1.0f / (1.0f + __expf(-t));
}

__device__ __forceinline__ void warp_sum8(float (&p)[8]) {
#pragma unroll
    for (int off = 16; off > 0; off >>= 1) {
#pragma unroll
        for (int j = 0; j < 8; ++j)
            p[j] += __shfl_xor_sync(0xffffffffu, p[j], off);
    }
}

// ---- K1: 64 rows per CTA, 4 warps x 16 rows, 2 pipelined batches ----
__global__ __launch_bounds__(128, 8)
void k1_fc1(const float* __restrict__ x,
            const float* __restrict__ W1,
            const float* __restrict__ b1)
{
    cudaTriggerProgrammaticLaunchCompletion();

    const int o     = blockIdx.x >> 2;       // 4 chunks of 64 rows
    const int chunk = blockIdx.x & 3;
    const int warp  = threadIdx.x >> 5;
    const int lane  = threadIdx.x & 31;

    const float4 xv =
        reinterpret_cast<const float4*>(x + (size_t)o * IN_DIM_)[lane];
    const int row0 = chunk * 64 + warp * 16;
    // row stride = 128 floats = 32 float4
    const float4* Wr = reinterpret_cast<const float4*>(
                           W1 + (size_t)o * MID_ * IN_DIM_ +
                           (size_t)row0 * IN_DIM_) + lane;

    // ---- batch 0: rows 0..7 ----
    float4 w[8];
#pragma unroll
    for (int j = 0; j < 8; ++j)
        w[j] = __ldcs(Wr + j * 32);

    float p0[8];
#pragma unroll
    for (int j = 0; j < 8; ++j)
        p0[j] = dot4(w[j], xv);

    // ---- issue batch 1 loads (rows 8..15) BEFORE reducing batch 0 ----
#pragma unroll
    for (int j = 0; j < 8; ++j)
        w[j] = __ldcs(Wr + (8 + j) * 32);

    warp_sum8(p0);   // 8 loads in flight underneath this SHFL chain

    if (lane == 0) {
        const float4* b1v =
            reinterpret_cast<const float4*>(b1 + o * MID_ + row0);
        const float4 ba = b1v[0];
        const float4 bb = b1v[1];
        float4* y1v = reinterpret_cast<float4*>(g_y1 + o * MID_ + row0);
        y1v[0] = make_float4(p0[0] + ba.x, p0[1] + ba.y,
                             p0[2] + ba.z, p0[3] + ba.w);
        y1v[1] = make_float4(p0[4] + bb.x, p0[5] + bb.y,
                             p0[6] + bb.z, p0[7] + bb.w);
    }

    // ---- batch 1 compute + reduce ----
    float p1[8];
#pragma unroll
    for (int j = 0; j < 8; ++j)
        p1[j] = dot4(w[j], xv);

    warp_sum8(p1);

    if (lane == 0) {
        const float4* b1v =
            reinterpret_cast<const float4*>(b1 + o * MID_ + row0 + 8);
        const float4 ba = b1v[0];
        const float4 bb = b1v[1];
        float4* y1v = reinterpret_cast<float4*>(g_y1 + o * MID_ + row0 + 8);
        y1v[0] = make_float4(p1[0] + ba.x, p1[1] + ba.y,
                             p1[2] + ba.z, p1[3] + ba.w);
        y1v[1] = make_float4(p1[4] + bb.x, p1[5] + bb.y,
                             p1[6] + bb.z, p1[7] + bb.w);
    }
}

// ---- K2: 32 rows per CTA, 128 thr, 2-row prefetch (R14 exact) ----
__global__ __launch_bounds__(128, 10)
void k2_fc2(const float* __restrict__ W2,
            const float* __restrict__ b2,
            const float* __restrict__ W3)
{
    cudaTriggerProgrammaticLaunchCompletion();

    const int o     = blockIdx.x >> 3;
    const int chunk = blockIdx.x & 7;
    const int warp  = threadIdx.x >> 5;
    const int lane  = threadIdx.x & 31;

    const int row0 = chunk * 32 + warp * 8;
    const float4* Wr = reinterpret_cast<const float4*>(
                           W2 + (size_t)o * MID_ * MID_ +
                           (size_t)row0 * MID_) + lane;

    // Prefetch rows 0,1 (pure input — legal pre-sync).
    const float4 p_a0 = __ldcs(Wr);
    const float4 p_a1 = __ldcs(Wr + 32);
    const float4 p_c0 = __ldcs(Wr + 64);
    const float4 p_c1 = __ldcs(Wr + 96);

    cudaGridDependencySynchronize();

    const float4* y1v = reinterpret_cast<const float4*>(g_y1 + o * MID_);
    const float4 ya = y1v[lane];
    const float4 yb = y1v[32 + lane];

    float part[8];
    part[0] = fmaf(p_a0.x, ya.x, fmaf(p_a0.y, ya.y, fmaf(p_a0.z, ya.z,
              fmaf(p_a0.w, ya.w, dot4(p_a1, yb)))));
    part[1] = fmaf(p_c0.x, ya.x, fmaf(p_c0.y, ya.y, fmaf(p_c0.z, ya.z,
              fmaf(p_c0.w, ya.w, dot4(p_c1, yb)))));

#pragma unroll
    for (int b = 1; b < 4; ++b) {
        const float4 a0 = __ldcs(Wr + (2 * b)     * 64);
        const float4 a1 = __ldcs(Wr + (2 * b)     * 64 + 32);
        const float4 c0 = __ldcs(Wr + (2 * b + 1) * 64);
        const float4 c1 = __ldcs(Wr + (2 * b + 1) * 64 + 32);
        part[2 * b]     = fmaf(a0.x, ya.x, fmaf(a0.y, ya.y, fmaf(a0.z, ya.z,
                          fmaf(a0.w, ya.w, dot4(a1, yb)))));
        part[2 * b + 1] = fmaf(c0.x, ya.x, fmaf(c0.y, ya.y, fmaf(c0.z, ya.z,
                          fmaf(c0.w, ya.w, dot4(c1, yb)))));
    }

    warp_sum8(part);

    __shared__ float sp[4];
    if (lane == 0) {
        const float* b2o = b2 + o * MID_ + row0;
        const float* W3o = W3 + o * MID_ + row0;
        float p = 0.0f;
#pragma unroll
        for (int j = 0; j < 8; ++j)
            p = fmaf(W3o[j], sigmoidf_(part[j] + b2o[j]), p);
        sp[warp] = p;
    }
    __syncthreads();   // convergent barrier
    if (threadIdx.x == 0)
        g_part[chunk * N_OBJ_ + o] = sp[0] + sp[1] + sp[2] + sp[3];
}

// ---- K3: thread-per-object reduction + sigmoid ----
__global__ __launch_bounds__(128)
void k3_final(const float* __restrict__ b3, float* __restrict__ out)
{
    cudaGridDependencySynchronize();

    const int o = blockIdx.x * 128 + threadIdx.x;
    float s = b3[o];
#pragma unroll
    for (int c = 0; c < 8; ++c)
        s += g_part[c * N_OBJ_ + o];
    out[o] = sigmoidf_(s);
}

extern "C" void kernel_launch(void* const* d_in, const int* in_sizes, int n_in,
                              void* d_out, int out_size)
{
    const float* x  = (const float*)d_in[0];
    const float* W1 = (const float*)d_in[1];
    const float* b1 = (const float*)d_in[2];
    const float* W2 = (const float*)d_in[3];
    const float* b2 = (const float*)d_in[4];
    const float* W3 = (const float*)d_in[5];
    const float* b3 = (const float*)d_in[6];
    float* out = (float*)d_out;

    k1_fc1<<<N_OBJ_ * 4, 128>>>(x, W1, b1);

    cudaLaunchAttribute attr[1];
    attr[0].id = cudaLaunchAttributeProgrammaticStreamSerialization;
    attr[0].val.programmaticStreamSerializationAllowed = 1;

    {
        cudaLaunchConfig_t cfg = {};
        cfg.gridDim  = dim3(N_OBJ_ * 8);
        cfg.blockDim = dim3(128);
        cfg.stream   = 0;
        cfg.attrs    = attr;
        cfg.numAttrs = 1;
        cudaLaunchKernelEx(&cfg, k2_fc2, W2, b2, W3);
    }
    {
        cudaLaunchConfig_t cfg = {};
        cfg.gridDim  = dim3(N_OBJ_ / 128);
        cfg.blockDim = dim3(128);
        cfg.stream   = 0;
        cfg.attrs    = attr;
        cfg.numAttrs = 1;
        cudaLaunchKernelEx(&cfg, k3_final, b3, out);
    }
}

// round 17
// speedup vs baseline: 1.0008x; 1.0008x over previous
#include <cuda_runtime.h>

// Batched per-object 3-layer MLP — 3 kernels, PDL-chained.
// R17: K1 reduction re-mapped to 8-lanes-per-row: one warp = 8 rows with
// only 6 SHFLs (3-step xor butterfly x 2 row-groups) instead of 40.
// Theory: K1 was SHFL-pipe-bound (~82% of crossbar issue), not DRAM-bound.
// K2/K3 identical to R14 (best known).
//
//   K1: y1 = W1 @ x + b1                    (256 MB stream, 256thr/64-row)
//   K2: 32 rows of y2 per CTA + W3 partial  (512 MB stream, 128thr/32-row)
//   K3: out[o] = sigmoid(sum partials + b3)

#define N_OBJ_  2048
#define IN_DIM_ 128
#define MID_    256

__device__ float g_y1[N_OBJ_ * MID_];
__device__ float g_part[8 * N_OBJ_];   // [chunk][object]

__device__ __forceinline__ float dot4(float4 a, float4 b) {
    return fmaf(a.x, b.x, fmaf(a.y, b.y, fmaf(a.z, b.z, a.w * b.w)));
}

__device__ __forceinline__ float sigmoidf_(float t) {
    return 1.0f / (1.0f + __expf(-t));
}

__device__ __forceinline__ void warp_sum8(float (&p)[8]) {
#pragma unroll
    for (int off = 16; off > 0; off >>= 1) {
#pragma unroll
        for (int j = 0; j < 8; ++j)
            p[j] += __shfl_xor_sync(0xffffffffu, p[j], off);
    }
}

// ---- K1: 64 rows/CTA, 8 warps; warp = 8 rows, 8 lanes per row ----
__global__ __launch_bounds__(256, 4)
void k1_fc1(const float* __restrict__ x,
            const float* __restrict__ W1,
            const float* __restrict__ b1)
{
    cudaTriggerProgrammaticLaunchCompletion();

    const int o     = blockIdx.x >> 2;       // 4 chunks of 64 rows
    const int chunk = blockIdx.x & 3;
    const int warp  = threadIdx.x >> 5;
    const int lane  = threadIdx.x & 31;
    const int sub   = lane >> 3;              // row-in-group (0..3)
    const int j     = lane & 7;               // float4 slot within row

    // x fragments for this lane's slots: j, j+8, j+16, j+24
    const float4* x4 = reinterpret_cast<const float4*>(x + (size_t)o * IN_DIM_);
    const float4 xf0 = x4[j];
    const float4 xf1 = x4[j + 8];
    const float4 xf2 = x4[j + 16];
    const float4 xf3 = x4[j + 24];

    const int row0 = chunk * 64 + warp * 8;
    const float4* Wb = reinterpret_cast<const float4*>(
                           W1 + (size_t)o * MID_ * IN_DIM_);
    // group 0: rows row0+sub ; group 1: rows row0+4+sub (32 float4 per row)
    const float4* R0 = Wb + (size_t)(row0 + sub)     * 32 + j;
    const float4* R1 = Wb + (size_t)(row0 + 4 + sub) * 32 + j;

    // 8 independent LDG.128 in flight
    const float4 a0 = __ldcs(R0),      a1 = __ldcs(R0 + 8);
    const float4 a2 = __ldcs(R0 + 16), a3 = __ldcs(R0 + 24);
    const float4 c0 = __ldcs(R1),      c1 = __ldcs(R1 + 8);
    const float4 c2 = __ldcs(R1 + 16), c3 = __ldcs(R1 + 24);

    float p0 = (dot4(a0, xf0) + dot4(a1, xf1)) + (dot4(a2, xf2) + dot4(a3, xf3));
    float p1 = (dot4(c0, xf0) + dot4(c1, xf1)) + (dot4(c2, xf2) + dot4(c3, xf3));

    // 3-step butterfly within each 8-lane group; 2 interleaved chains
#pragma unroll
    for (int off = 4; off > 0; off >>= 1) {
        p0 += __shfl_xor_sync(0xffffffffu, p0, off);
        p1 += __shfl_xor_sync(0xffffffffu, p1, off);
    }

    if (j == 0) {
        const int r0 = row0 + sub;          // lanes 0,8,16,24 -> 4 consecutive rows
        const int r1 = row0 + 4 + sub;
        g_y1[o * MID_ + r0] = p0 + b1[o * MID_ + r0];
        g_y1[o * MID_ + r1] = p1 + b1[o * MID_ + r1];
    }
}

// ---- K2: 32 rows per CTA, 128 thr, 2-row prefetch (R14 exact) ----
__global__ __launch_bounds__(128, 10)
void k2_fc2(const float* __restrict__ W2,
            const float* __restrict__ b2,
            const float* __restrict__ W3)
{
    cudaTriggerProgrammaticLaunchCompletion();

    const int o     = blockIdx.x >> 3;
    const int chunk = blockIdx.x & 7;
    const int warp  = threadIdx.x >> 5;
    const int lane  = threadIdx.x & 31;

    const int row0 = chunk * 32 + warp * 8;
    const float4* Wr = reinterpret_cast<const float4*>(
                           W2 + (size_t)o * MID_ * MID_ +
                           (size_t)row0 * MID_) + lane;

    // Prefetch rows 0,1 (pure input — legal pre-sync).
    const float4 p_a0 = __ldcs(Wr);
    const float4 p_a1 = __ldcs(Wr + 32);
    const float4 p_c0 = __ldcs(Wr + 64);
    const float4 p_c1 = __ldcs(Wr + 96);

    cudaGridDependencySynchronize();

    const float4* y1v = reinterpret_cast<const float4*>(g_y1 + o * MID_);
    const float4 ya = y1v[lane];
    const float4 yb = y1v[32 + lane];

    float part[8];
    part[0] = fmaf(p_a0.x, ya.x, fmaf(p_a0.y, ya.y, fmaf(p_a0.z, ya.z,
              fmaf(p_a0.w, ya.w, dot4(p_a1, yb)))));
    part[1] = fmaf(p_c0.x, ya.x, fmaf(p_c0.y, ya.y, fmaf(p_c0.z, ya.z,
              fmaf(p_c0.w, ya.w, dot4(p_c1, yb)))));

#pragma unroll
    for (int b = 1; b < 4; ++b) {
        const float4 a0 = __ldcs(Wr + (2 * b)     * 64);
        const float4 a1 = __ldcs(Wr + (2 * b)     * 64 + 32);
        const float4 c0 = __ldcs(Wr + (2 * b + 1) * 64);
        const float4 c1 = __ldcs(Wr + (2 * b + 1) * 64 + 32);
        part[2 * b]     = fmaf(a0.x, ya.x, fmaf(a0.y, ya.y, fmaf(a0.z, ya.z,
                          fmaf(a0.w, ya.w, dot4(a1, yb)))));
        part[2 * b + 1] = fmaf(c0.x, ya.x, fmaf(c0.y, ya.y, fmaf(c0.z, ya.z,
                          fmaf(c0.w, ya.w, dot4(c1, yb)))));
    }

    warp_sum8(part);

    __shared__ float sp[4];
    if (lane == 0) {
        const float* b2o = b2 + o * MID_ + row0;
        const float* W3o = W3 + o * MID_ + row0;
        float p = 0.0f;
#pragma unroll
        for (int j = 0; j < 8; ++j)
            p = fmaf(W3o[j], sigmoidf_(part[j] + b2o[j]), p);
        sp[warp] = p;
    }
    __syncthreads();   // convergent barrier
    if (threadIdx.x == 0)
        g_part[chunk * N_OBJ_ + o] = sp[0] + sp[1] + sp[2] + sp[3];
}

// ---- K3: thread-per-object reduction + sigmoid ----
__global__ __launch_bounds__(128)
void k3_final(const float* __restrict__ b3, float* __restrict__ out)
{
    cudaGridDependencySynchronize();

    const int o = blockIdx.x * 128 + threadIdx.x;
    float s = b3[o];
#pragma unroll
    for (int c = 0; c < 8; ++c)
        s += g_part[c * N_OBJ_ + o];
    out[o] = sigmoidf_(s);
}

extern "C" void kernel_launch(void* const* d_in, const int* in_sizes, int n_in,
                              void* d_out, int out_size)
{
    const float* x  = (const float*)d_in[0];
    const float* W1 = (const float*)d_in[1];
    const float* b1 = (const float*)d_in[2];
    const float* W2 = (const float*)d_in[3];
    const float* b2 = (const float*)d_in[4];
    const float* W3 = (const float*)d_in[5];
    const float* b3 = (const float*)d_in[6];
    float* out = (float*)d_out;

    k1_fc1<<<N_OBJ_ * 4, 256>>>(x, W1, b1);

    cudaLaunchAttribute attr[1];
    attr[0].id = cudaLaunchAttributeProgrammaticStreamSerialization;
    attr[0].val.programmaticStreamSerializationAllowed = 1;

    {
        cudaLaunchConfig_t cfg = {};
        cfg.gridDim  = dim3(N_OBJ_ * 8);
        cfg.blockDim = dim3(128);
        cfg.stream   = 0;
        cfg.attrs    = attr;
        cfg.numAttrs = 1;
        cudaLaunchKernelEx(&cfg, k2_fc2, W2, b2, W3);
    }
    {
        cudaLaunchConfig_t cfg = {};
        cfg.gridDim  = dim3(N_OBJ_ / 128);
        cfg.blockDim = dim3(128);
        cfg.stream   = 0;
        cfg.attrs    = attr;
        cfg.numAttrs = 1;
        cudaLaunchKernelEx(&cfg, k3_final, b3, out);
    }
}